// round 3
// baseline (speedup 1.0000x reference)
#include <cuda_runtime.h>
#include <cuda_bf16.h>
#include <cstdint>

// ---------------------------------------------------------------------------
// Fused two-tower scorer (mma.sync tf32 path — tcgen05 PTX not accepted by
// this harness's compute_103 PTX target):
//   out[b] = sum_l relu(U[x[b,0]]·uW[l]+ub[l]) * relu(I[x[b,1]]·iW[l]+ib[l])
// B=16384, F=512, L=256.  CTA: 128 rows x 256 latents, both towers.
// NOTE: x is int32 (JAX x64-disabled downcasts the requested int64).
// ---------------------------------------------------------------------------

#define NTHREADS 256
#define TB       128     // batch rows per CTA
#define LOUT     256     // latents (GEMM N)
#define KF       512     // features (GEMM K)
#define KC       32      // K chunk (floats)
#define NCHUNK   32      // 16 chunks/tower x 2 towers
#define AST      36      // A smem row stride (floats), conflict-free for 4g+t
#define WST      36      // W smem row stride (floats)
#define ULST     264     // user-latent smem stride (bf16 elems)

// smem byte offsets
#define S_IDXU   0
#define S_IDXI   512
#define S_UB     1024
#define S_IB     2048
#define S_PART   3072
#define S_ULAT   3584                    // 128 x 264 bf16 = 67584
#define S_A      71168                   // double-buffered A tiles
#define A_BYTES  (TB * AST * 4)          // 18432
#define S_W      (S_A + 2 * A_BYTES)     // 108032
#define W_BYTES  (LOUT * WST * 4)        // 36864
#define S_TOTAL  (S_W + 2 * W_BYTES)     // 181760

// --------------------------- helpers ----------------------------------------

__device__ __forceinline__ uint32_t s2u(const void* p) {
    uint32_t a;
    asm("{ .reg .u64 t; cvta.to.shared.u64 t, %1; cvt.u32.u64 %0, t; }"
        : "=r"(a) : "l"(p));
    return a;
}

// round-to-nearest tf32 (RZ truncation would add a coherent -1e-3 bias)
__device__ __forceinline__ uint32_t tf32r(float x) {
    uint32_t u;
    asm("cvt.rna.tf32.f32 %0, %1;" : "=r"(u) : "f"(x));
    return u;
}

__device__ __forceinline__ void mma8(float* c, const uint32_t* a,
                                     const uint32_t* b) {
    asm volatile(
        "mma.sync.aligned.m16n8k8.row.col.f32.tf32.tf32.f32 "
        "{%0,%1,%2,%3}, {%4,%5,%6,%7}, {%8,%9}, {%0,%1,%2,%3};"
        : "+f"(c[0]), "+f"(c[1]), "+f"(c[2]), "+f"(c[3])
        : "r"(a[0]), "r"(a[1]), "r"(a[2]), "r"(a[3]), "r"(b[0]), "r"(b[1]));
}

__device__ __forceinline__ void cp16(uint32_t dst, const float* src) {
    asm volatile("cp.async.cg.shared.global [%0], [%1], 16;"
                 :: "r"(dst), "l"(src) : "memory");
}

__device__ __forceinline__ void issue_chunk(
    int c, uint32_t sb, const char* smemc,
    const float* __restrict__ ulut, const float* __restrict__ ilut,
    const float* __restrict__ uW,   const float* __restrict__ iW, int tid) {
    const int tower = c >> 4;
    const int kc    = (c & 15) * KC;
    const int buf   = c & 1;
    const int* idx  = (const int*)(smemc + (tower ? S_IDXI : S_IDXU));
    const float* lut = tower ? ilut : ulut;
    const float* W   = tower ? iW   : uW;
    const uint32_t dA = sb + S_A + buf * A_BYTES;
    const uint32_t dW = sb + S_W + buf * W_BYTES;
#pragma unroll
    for (int i = 0; i < 4; i++) {            // A: 128 rows x 8 x 16B
        int seg = tid + i * NTHREADS;
        int row = seg >> 3, q = seg & 7;
        cp16(dA + row * (AST * 4) + q * 16,
             lut + (size_t)idx[row] * KF + kc + q * 4);
    }
#pragma unroll
    for (int i = 0; i < 8; i++) {            // W: 256 rows x 8 x 16B
        int seg = tid + i * NTHREADS;
        int row = seg >> 3, q = seg & 7;
        cp16(dW + row * (WST * 4) + q * 16,
             W + (size_t)row * KF + kc + q * 4);
    }
    asm volatile("cp.async.commit_group;" ::: "memory");
}

// --------------------------- kernel -----------------------------------------

__global__ void __launch_bounds__(NTHREADS, 1) towers_kernel(
    const int* __restrict__ x,
    const float* __restrict__ ulut, const float* __restrict__ ilut,
    const float* __restrict__ uW,   const float* __restrict__ ubias,
    const float* __restrict__ iW,   const float* __restrict__ ibias,
    float* __restrict__ out) {
    extern __shared__ char smem[];
    const uint32_t sb = s2u(smem);
    const int tid  = threadIdx.x;
    const int lane = tid & 31;
    const int wid  = tid >> 5;
    const int wm   = wid & 1;        // warp row (0..1) -> 64 rows each
    const int wn   = wid >> 1;       // warp col (0..3) -> 64 latents each
    const int g    = lane >> 2;      // group id (0..7)
    const int t    = lane & 3;       // thread-in-group (0..3)

    int*   idxu = (int*)(smem + S_IDXU);
    int*   idxi = (int*)(smem + S_IDXI);
    float* ubS  = (float*)(smem + S_UB);
    float* ibS  = (float*)(smem + S_IB);
    float* part = (float*)(smem + S_PART);
    __nv_bfloat16* ulat = (__nv_bfloat16*)(smem + S_ULAT);

    ubS[tid] = ubias[tid];
    ibS[tid] = ibias[tid];
    if (tid < TB) {
        part[tid] = 0.f;
        int gg = blockIdx.x * TB + tid;
        idxu[tid] = x[2 * gg];
        idxi[tid] = x[2 * gg + 1];
    }
    __syncthreads();

    issue_chunk(0, sb, smem, ulut, ilut, uW, iW, tid);

    float acc[4][8][4];
#pragma unroll
    for (int mt = 0; mt < 4; mt++)
#pragma unroll
        for (int nt = 0; nt < 8; nt++)
#pragma unroll
            for (int i = 0; i < 4; i++) acc[mt][nt][i] = 0.f;

    for (int c = 0; c < NCHUNK; c++) {
        if (c + 1 < NCHUNK) {
            issue_chunk(c + 1, sb, smem, ulut, ilut, uW, iW, tid);
            asm volatile("cp.async.wait_group 1;" ::: "memory");
        } else {
            asm volatile("cp.async.wait_group 0;" ::: "memory");
        }
        __syncthreads();

        const float* A  = (const float*)(smem + S_A + (c & 1) * A_BYTES);
        const float* Bs = (const float*)(smem + S_W + (c & 1) * W_BYTES);
#pragma unroll
        for (int s = 0; s < 4; s++) {        // 4 k-steps of 8
            const int k0 = s * 8 + t;
            uint32_t af[4][4];
#pragma unroll
            for (int mt = 0; mt < 4; mt++) {
                const int r0 = wm * 64 + mt * 16 + g;
                af[mt][0] = tf32r(A[r0 * AST + k0]);
                af[mt][1] = tf32r(A[(r0 + 8) * AST + k0]);
                af[mt][2] = tf32r(A[r0 * AST + k0 + 4]);
                af[mt][3] = tf32r(A[(r0 + 8) * AST + k0 + 4]);
            }
            uint32_t bf[8][2];
#pragma unroll
            for (int nt = 0; nt < 8; nt++) {
                const int n0 = wn * 64 + nt * 8 + g;
                bf[nt][0] = tf32r(Bs[n0 * WST + k0]);
                bf[nt][1] = tf32r(Bs[n0 * WST + k0 + 4]);
            }
#pragma unroll
            for (int mt = 0; mt < 4; mt++)
#pragma unroll
                for (int nt = 0; nt < 8; nt++)
                    mma8(acc[mt][nt], af[mt], bf[nt]);
        }

        if (c == NCHUNK / 2 - 1) {
            // user-tower epilogue: bias + relu -> bf16 smem, reset acc
#pragma unroll
            for (int mt = 0; mt < 4; mt++) {
                const int r0 = wm * 64 + mt * 16 + g;
#pragma unroll
                for (int nt = 0; nt < 8; nt++) {
                    const int c0 = wn * 64 + nt * 8 + 2 * t;
                    float u0 = fmaxf(acc[mt][nt][0] + ubS[c0],     0.f);
                    float u1 = fmaxf(acc[mt][nt][1] + ubS[c0 + 1], 0.f);
                    float u2 = fmaxf(acc[mt][nt][2] + ubS[c0],     0.f);
                    float u3 = fmaxf(acc[mt][nt][3] + ubS[c0 + 1], 0.f);
                    *(__nv_bfloat162*)(ulat + r0 * ULST + c0) =
                        __floats2bfloat162_rn(u0, u1);
                    *(__nv_bfloat162*)(ulat + (r0 + 8) * ULST + c0) =
                        __floats2bfloat162_rn(u2, u3);
                    acc[mt][nt][0] = acc[mt][nt][1] = 0.f;
                    acc[mt][nt][2] = acc[mt][nt][3] = 0.f;
                }
            }
        }
        __syncthreads();
    }

    // item-tower epilogue: bias+relu, product with user latent, row-reduce
#pragma unroll
    for (int mt = 0; mt < 4; mt++) {
        const int r0 = wm * 64 + mt * 16 + g;
        float s0 = 0.f, s1 = 0.f;
#pragma unroll
        for (int nt = 0; nt < 8; nt++) {
            const int c0 = wn * 64 + nt * 8 + 2 * t;
            float v0 = fmaxf(acc[mt][nt][0] + ibS[c0],     0.f);
            float v1 = fmaxf(acc[mt][nt][1] + ibS[c0 + 1], 0.f);
            float v2 = fmaxf(acc[mt][nt][2] + ibS[c0],     0.f);
            float v3 = fmaxf(acc[mt][nt][3] + ibS[c0 + 1], 0.f);
            float2 u01 = __bfloat1622float2(
                *(__nv_bfloat162*)(ulat + r0 * ULST + c0));
            float2 u23 = __bfloat1622float2(
                *(__nv_bfloat162*)(ulat + (r0 + 8) * ULST + c0));
            s0 = fmaf(u01.x, v0, fmaf(u01.y, v1, s0));
            s1 = fmaf(u23.x, v2, fmaf(u23.y, v3, s1));
        }
        s0 += __shfl_xor_sync(0xffffffffu, s0, 1);
        s0 += __shfl_xor_sync(0xffffffffu, s0, 2);
        s1 += __shfl_xor_sync(0xffffffffu, s1, 1);
        s1 += __shfl_xor_sync(0xffffffffu, s1, 2);
        if (t == 0) {
            atomicAdd(&part[r0], s0);
            atomicAdd(&part[r0 + 8], s1);
        }
    }
    __syncthreads();

    if (tid < TB) out[blockIdx.x * TB + tid] = part[tid];
}

// --------------------------- launch -----------------------------------------

extern "C" void kernel_launch(void* const* d_in, const int* in_sizes, int n_in,
                              void* d_out, int out_size) {
    const int* x      = (const int*)d_in[0];
    const float* ulut = (const float*)d_in[1];
    const float* ilut = (const float*)d_in[2];
    const float* uW   = (const float*)d_in[3];
    const float* ub   = (const float*)d_in[4];
    const float* iW   = (const float*)d_in[5];
    const float* ib   = (const float*)d_in[6];
    float* out        = (float*)d_out;

    cudaFuncSetAttribute(towers_kernel,
                         cudaFuncAttributeMaxDynamicSharedMemorySize, S_TOTAL);
    int grid = out_size / TB;   // 16384 / 128 = 128
    towers_kernel<<<grid, NTHREADS, S_TOTAL>>>(x, ulut, ilut, uW, ub, iW, ib,
                                               out);
}